// round 2
// baseline (speedup 1.0000x reference)
#include <cuda_runtime.h>
#include <cstdint>

#define TT 512
#define VV 32
#define NSTAGE 9
#define NTHR 128
#define F_LOG2E 1.4426950408889634f
#define F_LN2   0.6931471805599453f

__device__ __forceinline__ float ex2f_(float x){ float y; asm("ex2.approx.ftz.f32 %0, %1;" : "=f"(y) : "f"(x)); return y; }
__device__ __forceinline__ float lg2f_(float x){ float y; asm("lg2.approx.ftz.f32 %0, %1;" : "=f"(y) : "f"(x)); return y; }
__device__ __forceinline__ void cpasync16(float* s, const float* g){
  uint32_t sa = (uint32_t)__cvta_generic_to_shared(s);
  asm volatile("cp.async.cg.shared.global [%0], [%1], 16;" :: "r"(sa), "l"(g));
}

__global__ __launch_bounds__(NTHR, 1)
void lattice_crf_kernel(const float* __restrict__ scores,
                        const void*  __restrict__ targets_raw,
                        const float* __restrict__ w_tx,
                        const float* __restrict__ w_init,
                        const float* __restrict__ w_final,
                        const float* __restrict__ w_dur,
                        float* __restrict__ out)
{
  __shared__ float tile[NSTAGE][VV*VV];   // score tiles, cp.async pipeline
  __shared__ float part[2][4][VV];        // cross-warp partials, double buffered
  __shared__ float craw[VV*VV];           // w_tx + w_dur (natural log units)
  __shared__ int   tg[TT+1];
  __shared__ float scale_sm[2];           // stale renormalizer 2^{-e}, double buffered
  __shared__ float num_sm;

  const int b   = blockIdx.x;
  const int tid = threadIdx.x;
  const int j   = tid & 31;   // output column
  const int w   = tid >> 5;   // warp: owns rows i0..i0+7
  const int i0  = w * 8;
  const float* sb = scores + (size_t)b * TT * VV * VV;

  // ---- detect targets dtype (int64 vs jax-demoted int32): if int64, odd int32 words are all 0
  const int* t32 = (const int*)targets_raw;
  int is64 = 1;
  #pragma unroll
  for (int k = 1; k < 64; k += 2) if (t32[k] != 0) is64 = 0;

  // ---- init shared
  for (int k = tid; k < VV*VV; k += NTHR) craw[k] = w_tx[k] + w_dur[k];
  if (is64) {
    const long long* t64 = (const long long*)targets_raw;
    for (int k = tid; k < TT+1; k += NTHR) tg[k] = (int)t64[(size_t)b*(TT+1) + k];
  } else {
    for (int k = tid; k < TT+1; k += NTHR) tg[k] = t32[(size_t)b*(TT+1) + k];
  }
  // initial u^{(0)}[i] = exp(w_init[i]) in linear space, held as warp-0 partials
  part[0][w][j] = (w == 0) ? ex2f_(w_init[j] * F_LOG2E) : 0.f;
  if (tid == 0) scale_sm[0] = 1.0f;

  // ---- cp.async prologue: tiles 0..NSTAGE-2
  for (int p = 0; p < NSTAGE-1; ++p){
    cpasync16(&tile[p][tid*8],     sb + p*VV*VV + tid*8);
    cpasync16(&tile[p][tid*8 + 4], sb + p*VV*VV + tid*8 + 4);
    asm volatile("cp.async.commit_group;");
  }
  __syncthreads();

  float c2[8];                            // (w_tx+w_dur)*log2e for my 8 (i,j) cells
  #pragma unroll
  for (int d = 0; d < 8; ++d) c2[d] = craw[(i0+d)*VV + j] * F_LOG2E;

  int   A   = 0;     // tid 0: accumulated integer log2-shift
  float num = 0.f;   // tid 32: numerator path score

  for (int t = 0; t < TT; ++t){
    const int slot = t % NSTAGE;
    asm volatile("cp.async.wait_group %0;" :: "n"(NSTAGE-2));   // tile t arrived
    __syncthreads();  // tile t visible; everyone done with iter t-1 (slot & partial reuse safe)

    { // issue tile t+NSTAGE-1 into the slot consumed at iter t-1
      int tl = t + NSTAGE - 1;
      if (tl < TT){
        int ds = tl % NSTAGE;
        cpasync16(&tile[ds][tid*8],     sb + (size_t)tl*VV*VV + tid*8);
        cpasync16(&tile[ds][tid*8 + 4], sb + (size_t)tl*VV*VV + tid*8 + 4);
      }
      asm volatile("cp.async.commit_group;");  // empty groups keep the count consistent
    }

    const int pb = t & 1;
    const float sc = scale_sm[pb];

    // reduce cross-warp partials -> my 8 u values (broadcast LDS.128, no bank conflicts)
    float4 a0 = *(const float4*)&part[pb][0][i0];
    float4 a1 = *(const float4*)&part[pb][1][i0];
    float4 a2 = *(const float4*)&part[pb][2][i0];
    float4 a3 = *(const float4*)&part[pb][3][i0];
    float4 b0 = *(const float4*)&part[pb][0][i0+4];
    float4 b1 = *(const float4*)&part[pb][1][i0+4];
    float4 b2 = *(const float4*)&part[pb][2][i0+4];
    float4 b3 = *(const float4*)&part[pb][3][i0+4];
    float u[8];
    u[0] = ((a0.x+a1.x)+(a2.x+a3.x))*sc;
    u[1] = ((a0.y+a1.y)+(a2.y+a3.y))*sc;
    u[2] = ((a0.z+a1.z)+(a2.z+a3.z))*sc;
    u[3] = ((a0.w+a1.w)+(a2.w+a3.w))*sc;
    u[4] = ((b0.x+b1.x)+(b2.x+b3.x))*sc;
    u[5] = ((b0.y+b1.y)+(b2.y+b3.y))*sc;
    u[6] = ((b0.z+b1.z)+(b2.z+b3.z))*sc;
    u[7] = ((b0.w+b1.w)+(b2.w+b3.w))*sc;

    const float* tp = &tile[slot][0];
    float accA = 0.f, accB = 0.f;
    #pragma unroll
    for (int d = 0; d < 8; d += 2){
      float x0 = fmaf(tp[(i0+d  )*VV + j], F_LOG2E, c2[d  ]);
      float x1 = fmaf(tp[(i0+d+1)*VV + j], F_LOG2E, c2[d+1]);
      accA = fmaf(ex2f_(x0), u[d  ], accA);
      accB = fmaf(ex2f_(x1), u[d+1], accB);
    }
    float acc = accA + accB;

    if (tid == 0){
      // account the shift just consumed (sc = 2^{-e} -> e = 127 - exp_field)
      A += 127 - ((__float_as_int(sc) >> 23) & 255);
      // stale renormalizer for next step from observed magnitude (acc ~= u_out[0]/4)
      int e = ((__float_as_int(acc) >> 23) & 255) - 127 + 2;
      e = max(-120, min(120, e));
      scale_sm[pb ^ 1] = __int_as_float((127 - e) << 23);
    }
    if (tid == 32){
      int s_ = tg[t], d_ = tg[t+1];
      num += tp[s_*VV + d_] + craw[s_*VV + d_];
    }
    part[pb ^ 1][w][j] = acc;
  }

  __syncthreads();
  if (tid == 32) num_sm = num + w_init[tg[0]] + w_final[tg[TT]];
  __syncthreads();

  if (w == 0){
    // final partials landed in buffer (TT & 1) = 0
    float r = part[0][0][j] + part[0][1][j] + part[0][2][j] + part[0][3][j];
    float term = r * ex2f_(w_final[j] * F_LOG2E);
    #pragma unroll
    for (int off = 16; off; off >>= 1)
      term += __shfl_xor_sync(0xffffffffu, term, off);
    if (j == 0){
      float log2den = lg2f_(term) + (float)A;
      out[b] = num_sm - F_LN2 * log2den;
    }
  }
}

extern "C" void kernel_launch(void* const* d_in, const int* in_sizes, int n_in,
                              void* d_out, int out_size)
{
  const float* scores  = (const float*)d_in[0];
  const void*  targets = d_in[1];
  const float* w_tx    = (const float*)d_in[2];
  const float* w_init  = (const float*)d_in[3];
  const float* w_final = (const float*)d_in[4];
  const float* w_dur   = (const float*)d_in[5];
  float* out = (float*)d_out;

  lattice_crf_kernel<<<64, NTHR>>>(scores, targets, w_tx, w_init, w_final, w_dur, out);
}

// round 3
// speedup vs baseline: 1.0542x; 1.0542x over previous
#include <cuda_runtime.h>
#include <cstdint>

#define TT 512
#define VV 32
#define NST 10
#define NTHR 128
#define F_LOG2E 1.4426950408889634f
#define F_LN2   0.6931471805599453f

typedef unsigned long long ull;

__device__ __forceinline__ float ex2f_(float x){ float y; asm("ex2.approx.ftz.f32 %0, %1;" : "=f"(y) : "f"(x)); return y; }
__device__ __forceinline__ float lg2f_(float x){ float y; asm("lg2.approx.ftz.f32 %0, %1;" : "=f"(y) : "f"(x)); return y; }
__device__ __forceinline__ ull add2_(ull a, ull b){ ull r; asm("add.rn.f32x2 %0, %1, %2;" : "=l"(r) : "l"(a), "l"(b)); return r; }
__device__ __forceinline__ ull mul2_(ull a, ull b){ ull r; asm("mul.rn.f32x2 %0, %1, %2;" : "=l"(r) : "l"(a), "l"(b)); return r; }
__device__ __forceinline__ ull fma2_(ull a, ull b, ull c){ ull r; asm("fma.rn.f32x2 %0, %1, %2, %3;" : "=l"(r) : "l"(a), "l"(b), "l"(c)); return r; }
__device__ __forceinline__ ull pack2_(float lo, float hi){ ull r; asm("mov.b64 %0, {%1, %2};" : "=l"(r) : "f"(lo), "f"(hi)); return r; }
__device__ __forceinline__ void unpack2_(ull v, float& lo, float& hi){ asm("mov.b64 {%0, %1}, %2;" : "=f"(lo), "=f"(hi) : "l"(v)); }
__device__ __forceinline__ void cpasync16(float* s, const float* g){
  uint32_t sa = (uint32_t)__cvta_generic_to_shared(s);
  asm volatile("cp.async.cg.shared.global [%0], [%1], 16;" :: "r"(sa), "l"(g));
}

__global__ __launch_bounds__(NTHR, 1)
void lattice_crf_kernel(const float* __restrict__ scores,
                        const void*  __restrict__ targets_raw,
                        const float* __restrict__ w_tx,
                        const float* __restrict__ w_init,
                        const float* __restrict__ w_final,
                        const float* __restrict__ w_dur,
                        float* __restrict__ out)
{
  __shared__ __align__(16) float tile[NST][VV*VV];  // cp.async pipeline of score tiles
  __shared__ __align__(16) float part[2][4][VV];    // cross-warp partials, double buffered
  __shared__ __align__(16) float craw[VV*VV];       // w_tx + w_dur
  __shared__ int   tg[TT+1];
  __shared__ float num_sm;

  const int b   = blockIdx.x;
  const int tid = threadIdx.x;
  const int j   = tid & 31;   // column
  const int w   = tid >> 5;   // warp owns rows [8w, 8w+8)
  const int i0  = w * 8;
  const float* sb = scores + (size_t)b * TT * VV * VV;

  // targets dtype detection (int64 vs demoted int32)
  const int* t32 = (const int*)targets_raw;
  int is64 = 1;
  #pragma unroll
  for (int k = 1; k < 64; k += 2) if (t32[k] != 0) is64 = 0;

  for (int k = tid; k < VV*VV; k += NTHR) craw[k] = w_tx[k] + w_dur[k];
  if (is64) {
    const long long* t64 = (const long long*)targets_raw;
    for (int k = tid; k < TT+1; k += NTHR) tg[k] = (int)t64[(size_t)b*(TT+1) + k];
  } else {
    for (int k = tid; k < TT+1; k += NTHR) tg[k] = t32[(size_t)b*(TT+1) + k];
  }
  // u0 = exp(w_init) held as warp-0 partials
  part[0][w][j] = (w == 0) ? ex2f_(w_init[j] * F_LOG2E) : 0.f;

  // cp.async prologue: tiles 0..NST-2 (NST-1 groups)
  for (int p = 0; p < NST-1; ++p){
    cpasync16(&tile[p][tid*8],     sb + p*VV*VV + tid*8);
    cpasync16(&tile[p][tid*8 + 4], sb + p*VV*VV + tid*8 + 4);
    asm volatile("cp.async.commit_group;");
  }
  __syncthreads();   // init visibility

  float c2[8];
  #pragma unroll
  for (int d = 0; d < 8; ++d) c2[d] = craw[(i0+d)*VV + j] * F_LOG2E;

  // e_0 from tile 0 (own-warp rows only -> warp-level sync suffices)
  asm volatile("cp.async.wait_group %0;" :: "n"(NST-2));
  __syncwarp();
  float e_[8];
  #pragma unroll
  for (int d = 0; d < 8; ++d)
    e_[d] = ex2f_(fmaf(tile[0][(i0+d)*VV + j], F_LOG2E, c2[d]));

  int   A   = 0;     // accumulated log2 renorm shift (identical in all threads)
  float num = 0.f;   // numerator (thread 32)
  int s_cur = 0, s_nxt = 1, s_wr = NST-1;

  #pragma unroll 2
  for (int t = 0; t < TT; ++t){
    // ---- pre-barrier: compute e for step t+1 (independent of u_t) ----
    asm volatile("cp.async.wait_group %0;" :: "n"(NST-3));   // tile t+1 arrived
    __syncwarp();
    const float* tn = &tile[s_nxt][0];
    float en[8];
    #pragma unroll
    for (int d = 0; d < 8; ++d)
      en[d] = ex2f_(fmaf(tn[(i0+d)*VV + j], F_LOG2E, c2[d]));

    __syncthreads();   // partials of step t are visible; old tile slots reusable

    // ---- consume u_t with e_t ----
    const int pb = t & 1;
    const float* pp = &part[pb][0][0];
    ulonglong2 p0 = *(const ulonglong2*)(pp + 0*VV + i0);
    ulonglong2 p1 = *(const ulonglong2*)(pp + 1*VV + i0);
    ulonglong2 p2 = *(const ulonglong2*)(pp + 2*VV + i0);
    ulonglong2 p3 = *(const ulonglong2*)(pp + 3*VV + i0);
    ulonglong2 q0 = *(const ulonglong2*)(pp + 0*VV + i0 + 4);
    ulonglong2 q1 = *(const ulonglong2*)(pp + 1*VV + i0 + 4);
    ulonglong2 q2 = *(const ulonglong2*)(pp + 2*VV + i0 + 4);
    ulonglong2 q3 = *(const ulonglong2*)(pp + 3*VV + i0 + 4);

    ull uA = add2_(add2_(p0.x, p1.x), add2_(p2.x, p3.x));  // u[0],u[1]
    ull uB = add2_(add2_(p0.y, p1.y), add2_(p2.y, p3.y));  // u[2],u[3]
    ull uC = add2_(add2_(q0.x, q1.x), add2_(q2.x, q3.x));  // u[4],u[5]
    ull uD = add2_(add2_(q0.y, q1.y), add2_(q2.y, q3.y));  // u[6],u[7]

    // local renormalizer from broadcast u_total[0] (exact 2^-esh, same in all threads)
    float ut0 = (pp[0] + pp[VV]) + (pp[2*VV] + pp[3*VV]);
    int esh = ((__float_as_int(ut0) >> 23) & 255) - 127;
    esh = esh < -126 ? -126 : (esh > 126 ? 126 : esh);
    float sc = __int_as_float((127 - esh) << 23);
    A += esh;

    ull e01 = pack2_(e_[0], e_[1]);
    ull e23 = pack2_(e_[2], e_[3]);
    ull e45 = pack2_(e_[4], e_[5]);
    ull e67 = pack2_(e_[6], e_[7]);
    ull m0 = fma2_(e23, uB, mul2_(e01, uA));
    ull m1 = fma2_(e67, uD, mul2_(e45, uC));
    ull m  = add2_(m0, m1);
    float lo, hi; unpack2_(m, lo, hi);
    float acc = (lo + hi) * sc;
    part[pb ^ 1][w][j] = acc;

    // numerator gather for step t (tile t still resident; overwrite happens next iter post-bar)
    if (tid == 32){
      int idx = tg[t]*VV + tg[t+1];
      num += tile[s_cur][idx] + craw[idx];
    }

    // ---- prefetch tile t+NST-1 into slot (t-1)%NST (dead after bar_t) ----
    {
      int tl = t + NST - 1;
      if (tl < TT){
        float* dsp = &tile[s_wr][0];
        const float* g = sb + (size_t)tl*VV*VV;
        cpasync16(dsp + tid*8,     g + tid*8);
        cpasync16(dsp + tid*8 + 4, g + tid*8 + 4);
      }
      asm volatile("cp.async.commit_group;");   // always commit to keep counts aligned
    }

    #pragma unroll
    for (int d = 0; d < 8; ++d) e_[d] = en[d];
    s_cur = s_nxt;
    s_nxt = (s_nxt+1 == NST) ? 0 : s_nxt+1;
    s_wr  = (s_wr +1 == NST) ? 0 : s_wr +1;
  }

  __syncthreads();
  if (tid == 32) num_sm = num + w_init[tg[0]] + w_final[tg[TT]];
  __syncthreads();

  if (w == 0){
    // final u landed in buffer 0 (TT even)
    float r = part[0][0][j] + part[0][1][j] + part[0][2][j] + part[0][3][j];
    float term = r * ex2f_(w_final[j] * F_LOG2E);
    #pragma unroll
    for (int off = 16; off; off >>= 1)
      term += __shfl_xor_sync(0xffffffffu, term, off);
    if (j == 0){
      float log2den = lg2f_(term) + (float)A;
      out[b] = num_sm - F_LN2 * log2den;
    }
  }
}

extern "C" void kernel_launch(void* const* d_in, const int* in_sizes, int n_in,
                              void* d_out, int out_size)
{
  const float* scores  = (const float*)d_in[0];
  const void*  targets = d_in[1];
  const float* w_tx    = (const float*)d_in[2];
  const float* w_init  = (const float*)d_in[3];
  const float* w_final = (const float*)d_in[4];
  const float* w_dur   = (const float*)d_in[5];
  float* out = (float*)d_out;

  lattice_crf_kernel<<<64, NTHR>>>(scores, targets, w_tx, w_init, w_final, w_dur, out);
}